// round 5
// baseline (speedup 1.0000x reference)
#include <cuda_runtime.h>
#include <cuda_fp16.h>
#include <cstdint>

#define BB 4
#define CC 64
#define NNPOS 4096
#define HH 64
#define WW 64

// Scratch (__device__ globals; no allocs allowed)
__device__ __half g_xn[BB * CC * NNPOS];           // LN output (B,C,N) fp16
__device__ __half g_q[BB * NNPOS * CC];            // Q fp16 (B,N,C), x (0.125*log2e) folded
__device__ __half g_k[BB * NNPOS * CC];            // K fp16 (B,N,C)
__device__ __half g_v[BB * CC * NNPOS];            // V fp16 (B,C,N)
__device__ float g_o[BB * NNPOS * CC];             // attn out (B,N,C) fp32

#define QSCALE 0.18033688011112293f   // 0.125 * log2(e)

// ---------------- helpers ----------------
__device__ __forceinline__ uint32_t h2u(__half2 h) { return *reinterpret_cast<uint32_t*>(&h); }

__device__ __forceinline__ void ldsm4(uint32_t* r, uint32_t addr) {
    asm volatile("ldmatrix.sync.aligned.m8n8.x4.shared.b16 {%0,%1,%2,%3}, [%4];"
                 : "=r"(r[0]), "=r"(r[1]), "=r"(r[2]), "=r"(r[3]) : "r"(addr));
}
__device__ __forceinline__ void mma16816(float* d, const uint32_t* a, uint32_t b0, uint32_t b1) {
    asm volatile("mma.sync.aligned.m16n8k16.row.col.f32.f16.f16.f32 "
                 "{%0,%1,%2,%3},{%4,%5,%6,%7},{%8,%9},{%0,%1,%2,%3};"
                 : "+f"(d[0]), "+f"(d[1]), "+f"(d[2]), "+f"(d[3])
                 : "r"(a[0]), "r"(a[1]), "r"(a[2]), "r"(a[3]), "r"(b0), "r"(b1));
}
__device__ __forceinline__ void cpasync16(uint32_t dst, const void* src) {
    asm volatile("cp.async.cg.shared.global [%0], [%1], 16;" :: "r"(dst), "l"(src));
}
__device__ __forceinline__ void cpcommit() { asm volatile("cp.async.commit_group;"); }
__device__ __forceinline__ void cpwait0()  { asm volatile("cp.async.wait_group 0;"); }

// fast 2^s in fma/alu pipes (no MUFU). |s| < 2^21.
__device__ __forceinline__ float exp2_fast(float s, float& lacc) {
    float t = s + 12582912.0f;
    int ii = __float_as_int(t) << 23;
    float f = s - (t - 12582912.0f);
    float p = fmaf(f, 0.00961812911f, 0.0555041087f);
    p = fmaf(f, p, 0.2402265070f);
    p = fmaf(f, p, 0.69314718056f);
    p = fmaf(f, p, 1.0f);
    p = __int_as_float(__float_as_int(p) + ii);
    lacc += p;
    return p;
}

// ---------------------------------------------------------------------------
// 1) LayerNorm over channels -> g_xn (B,C,N) fp16
// ---------------------------------------------------------------------------
__global__ void ln_kernel(const float* __restrict__ x,
                          const float* __restrict__ g,
                          const float* __restrict__ be) {
    int idx = blockIdx.x * blockDim.x + threadIdx.x;
    int b = idx >> 12;
    int i = idx & 4095;
    const float* xp = x + (size_t)b * CC * NNPOS + i;
    float vals[CC];
    float s = 0.f;
#pragma unroll
    for (int c = 0; c < CC; c++) { vals[c] = xp[(size_t)c * NNPOS]; s += vals[c]; }
    float mu = s * (1.f / 64.f);
    float vs = 0.f;
#pragma unroll
    for (int c = 0; c < CC; c++) { float d = vals[c] - mu; vs += d * d; }
    float rstd = rsqrtf(vs * (1.f / 64.f) + 1e-5f);
    __half* op = g_xn + (size_t)b * CC * NNPOS + i;
#pragma unroll
    for (int c = 0; c < CC; c++)
        op[(size_t)c * NNPOS] = __float2half_rn((vals[c] - mu) * rstd * __ldg(&g[c]) + __ldg(&be[c]));
}

// ---------------------------------------------------------------------------
// 2) q = (wq @ xn + bq) * QSCALE -> fp16 (B,N,C)
// ---------------------------------------------------------------------------
__global__ __launch_bounds__(256) void qproj_kernel(const float* __restrict__ wq,
                                                    const float* __restrict__ bq) {
    __shared__ float Xs[CC * 64];
    __shared__ float Wsm[CC * CC];
    int b = blockIdx.y;
    int i0 = blockIdx.x * 64;
    int tid = threadIdx.x;
    for (int t = tid; t < CC * CC / 4; t += 256)
        ((float4*)Wsm)[t] = ((const float4*)wq)[t];
    const __half* xp = g_xn + (size_t)b * CC * NNPOS + i0;
    for (int t = tid; t < CC * 16; t += 256) {
        int c = t >> 4, f = t & 15;
        uint2 raw = *(const uint2*)&xp[(size_t)c * NNPOS + f * 4];
        __half2 ha = *(__half2*)&raw.x, hb = *(__half2*)&raw.y;
        float2 fa = __half22float2(ha), fb = __half22float2(hb);
        *(float4*)&Xs[c * 64 + f * 4] = make_float4(fa.x, fa.y, fb.x, fb.y);
    }
    __syncthreads();
    int to = tid >> 4, tx = tid & 15;
    float acc[4][4] = {};
#pragma unroll 8
    for (int c = 0; c < CC; c++) {
        float4 xv = *(float4*)&Xs[c * 64 + tx * 4];
        float w0 = Wsm[(to * 4 + 0) * 64 + c];
        float w1 = Wsm[(to * 4 + 1) * 64 + c];
        float w2 = Wsm[(to * 4 + 2) * 64 + c];
        float w3 = Wsm[(to * 4 + 3) * 64 + c];
        acc[0][0] += w0 * xv.x; acc[0][1] += w0 * xv.y; acc[0][2] += w0 * xv.z; acc[0][3] += w0 * xv.w;
        acc[1][0] += w1 * xv.x; acc[1][1] += w1 * xv.y; acc[1][2] += w1 * xv.z; acc[1][3] += w1 * xv.w;
        acc[2][0] += w2 * xv.x; acc[2][1] += w2 * xv.y; acc[2][2] += w2 * xv.z; acc[2][3] += w2 * xv.w;
        acc[3][0] += w3 * xv.x; acc[3][1] += w3 * xv.y; acc[3][2] += w3 * xv.z; acc[3][3] += w3 * xv.w;
    }
    float bb[4];
#pragma unroll
    for (int r = 0; r < 4; r++) bb[r] = __ldg(&bq[to * 4 + r]);
#pragma unroll
    for (int s = 0; s < 4; s++) {
        int i = i0 + tx * 4 + s;
        float v0 = (acc[0][s] + bb[0]) * QSCALE;
        float v1 = (acc[1][s] + bb[1]) * QSCALE;
        float v2 = (acc[2][s] + bb[2]) * QSCALE;
        float v3 = (acc[3][s] + bb[3]) * QSCALE;
        size_t base = (size_t)(b * NNPOS + i) * CC + to * 4;
        *(uint2*)&g_q[base] = make_uint2(h2u(__floats2half2_rn(v0, v1)),
                                         h2u(__floats2half2_rn(v2, v3)));
    }
}

// ---------------------------------------------------------------------------
// 3) Depthwise 3x3: k -> fp16 (B,N,C), v -> fp16 (B,C,N)
// ---------------------------------------------------------------------------
__global__ __launch_bounds__(128) void dwconv_kernel(const float* __restrict__ wk,
                                                     const float* __restrict__ bk,
                                                     const float* __restrict__ wv,
                                                     const float* __restrict__ bv) {
    int t = threadIdx.x;
    int pos = blockIdx.x * 128 + t;
    int cg = blockIdx.y * 16;
    int b = blockIdx.z;
    int h = pos >> 6, w = pos & 63;
    uint32_t khp[8];
    uint32_t khprev = 0;
#pragma unroll
    for (int ci = 0; ci < 16; ci++) {
        int c = cg + ci;
        const __half* xp = g_xn + (size_t)(b * CC + c) * NNPOS;
        const float* wkp = wk + c * 9;
        const float* wvp = wv + c * 9;
        float sk = __ldg(&bk[c]);
        float sv = __ldg(&bv[c]);
#pragma unroll
        for (int dh = 0; dh < 3; dh++) {
            int hh = h + dh - 1;
            if (hh < 0 || hh >= HH) continue;
#pragma unroll
            for (int dw = 0; dw < 3; dw++) {
                int ww = w + dw - 1;
                if (ww < 0 || ww >= WW) continue;
                float xv = __half2float(xp[hh * WW + ww]);
                sk += xv * __ldg(&wkp[dh * 3 + dw]);
                sv += xv * __ldg(&wvp[dh * 3 + dw]);
            }
        }
        g_v[(size_t)(b * CC + c) * NNPOS + pos] = __float2half_rn(sv);
        uint32_t hb = (uint32_t)__half_as_ushort(__float2half_rn(sk));
        if (ci & 1) khp[ci >> 1] = khprev | (hb << 16);
        else khprev = hb;
    }
    size_t kbase = (size_t)(b * NNPOS + pos) * CC + cg;
    *(uint4*)&g_k[kbase]     = make_uint4(khp[0], khp[1], khp[2], khp[3]);
    *(uint4*)&g_k[kbase + 8] = make_uint4(khp[4], khp[5], khp[6], khp[7]);
}

// ---------------------------------------------------------------------------
// 4) HMMA flash attention, fp16 operands, fp32 accum.
//    grid (64, B) = 256 blocks, 128 threads = 4 warps x 16 query rows.
//    2 CTAs/SM; K tile 128x(128B+16), V tile 64x(256B+16), double buffered.
// ---------------------------------------------------------------------------
#define KROWB 144
#define VROWB 272
#define KBYTES (128 * KROWB)        // 18432
#define VBYTES (64 * VROWB)         // 17408
#define BUFB (KBYTES + VBYTES)      // 35840
#define ATTN_SMEM (2 * BUFB)        // 71680

__device__ __forceinline__ void prefetch_tile(char* smp, int s, int b, int jt, int tid) {
    // K: 128 rows x 128B. thread -> row j = tid (128B each)
    {
        const __half* src = g_k + (size_t)(b * NNPOS + jt + tid) * CC;
        uint32_t dst = (uint32_t)__cvta_generic_to_shared(smp + s * BUFB + tid * KROWB);
#pragma unroll
        for (int u = 0; u < 8; u++) cpasync16(dst + u * 16, src + u * 8);
    }
    // V: 64 rows x 256B. thread -> row c = tid>>1, half q = tid&1 (128B each)
    {
        int c = tid >> 1, q = tid & 1;
        const __half* src = g_v + (size_t)(b * CC + c) * NNPOS + jt + q * 64;
        uint32_t dst = (uint32_t)__cvta_generic_to_shared(smp + s * BUFB + KBYTES + c * VROWB + q * 128);
#pragma unroll
        for (int u = 0; u < 8; u++) cpasync16(dst + u * 16, src + u * 8);
    }
}

__global__ __launch_bounds__(128, 1) void attn_kernel() {
    extern __shared__ char smp[];
    int tid = threadIdx.x;
    int w = tid >> 5, lane = tid & 31;
    int b = blockIdx.y;
    int i0 = blockIdx.x * 64;
    int g = lane >> 2, t4 = lane & 3;

    // B-type ldmatrix.x4 lane offset pieces
    int laneRowB = (lane & 7) + ((lane & 16) >> 1);
    int laneKB   = (lane & 8) << 1;
    uint32_t loffK = (uint32_t)(laneRowB * KROWB + laneKB);
    uint32_t loffV = (uint32_t)(laneRowB * VROWB + laneKB);
    uint32_t smbase = (uint32_t)__cvta_generic_to_shared(smp);

    prefetch_tile(smp, 0, b, 0, tid);
    cpcommit();

    // Q A-fragments resident: qA[ks][0..3], ks = 0..3 (K=64)
    uint32_t qA[4][4];
    {
        size_t row0 = (size_t)(b * NNPOS + i0 + w * 16 + g) * CC;
        size_t row8 = row0 + 8 * CC;
#pragma unroll
        for (int ks = 0; ks < 4; ks++) {
            int col = 2 * t4 + 16 * ks;
            qA[ks][0] = *(const uint32_t*)(g_q + row0 + col);
            qA[ks][1] = *(const uint32_t*)(g_q + row8 + col);
            qA[ks][2] = *(const uint32_t*)(g_q + row0 + col + 8);
            qA[ks][3] = *(const uint32_t*)(g_q + row8 + col + 8);
        }
    }

    float oacc[8][4] = {};
    float l0 = 0.f, l1 = 0.f;

    for (int tix = 0; tix < 32; tix++) {
        cpwait0();
        __syncthreads();
        if (tix < 31) { prefetch_tile(smp, (tix + 1) & 1, b, (tix + 1) * 128, tid); cpcommit(); }

        uint32_t kb = smbase + (uint32_t)((tix & 1) * BUFB) + loffK;
        uint32_t vb = smbase + (uint32_t)((tix & 1) * BUFB + KBYTES) + loffV;

        // ---- S = Q K^T : M=16 x N=128, K=64, ldsm double-buffered ----
        float sacc[16][4] = {};
        {
            uint32_t b4[2][4];
            ldsm4(b4[0], kb);
#pragma unroll
            for (int it = 0; it < 32; it++) {
                int ks = it >> 3, np = it & 7;
                int cur = it & 1;
                if (it < 31) {
                    int nx = it + 1;
                    ldsm4(b4[cur ^ 1], kb + (uint32_t)((nx & 7) * (16 * KROWB) + (nx >> 3) * 32));
                }
                mma16816(sacc[2 * np],     qA[ks], b4[cur][0], b4[cur][1]);
                mma16816(sacc[2 * np + 1], qA[ks], b4[cur][2], b4[cur][3]);
            }
        }

        // ---- p = 2^S fused into O += P V^T : M=16 x N=64, K=128 ----
        {
            uint32_t v4[2][4];
            ldsm4(v4[0], vb);
#pragma unroll
            for (int ks2 = 0; ks2 < 8; ks2++) {
                uint32_t pA[4];
                {
                    float* se = sacc[2 * ks2];
                    float* so = sacc[2 * ks2 + 1];
                    float p0 = exp2_fast(se[0], l0), p1 = exp2_fast(se[1], l0);
                    float p2 = exp2_fast(se[2], l1), p3 = exp2_fast(se[3], l1);
                    float p4 = exp2_fast(so[0], l0), p5 = exp2_fast(so[1], l0);
                    float p6 = exp2_fast(so[2], l1), p7 = exp2_fast(so[3], l1);
                    pA[0] = h2u(__floats2half2_rn(p0, p1));
                    pA[1] = h2u(__floats2half2_rn(p2, p3));
                    pA[2] = h2u(__floats2half2_rn(p4, p5));
                    pA[3] = h2u(__floats2half2_rn(p6, p7));
                }
#pragma unroll
                for (int np = 0; np < 4; np++) {
                    int it = ks2 * 4 + np;
                    int cur = it & 1;
                    if (it < 31) {
                        int nx = it + 1;
                        ldsm4(v4[cur ^ 1], vb + (uint32_t)((nx & 3) * (16 * VROWB) + (nx >> 2) * 32));
                    }
                    mma16816(oacc[2 * np],     pA, v4[cur][0], v4[cur][1]);
                    mma16816(oacc[2 * np + 1], pA, v4[cur][2], v4[cur][3]);
                }
            }
        }
    }

    // reduce l over the 4 lanes sharing each row
    l0 += __shfl_xor_sync(0xffffffffu, l0, 1);
    l0 += __shfl_xor_sync(0xffffffffu, l0, 2);
    l1 += __shfl_xor_sync(0xffffffffu, l1, 1);
    l1 += __shfl_xor_sync(0xffffffffu, l1, 2);
    float inv0 = 1.f / l0, inv1 = 1.f / l1;

    float* orow0 = g_o + (size_t)(b * NNPOS + i0 + w * 16 + g) * CC;
    float* orow8 = orow0 + 8 * CC;
#pragma unroll
    for (int nt = 0; nt < 8; nt++) {
        int c = nt * 8 + 2 * t4;
        *(float2*)&orow0[c] = make_float2(oacc[nt][0] * inv0, oacc[nt][1] * inv0);
        *(float2*)&orow8[c] = make_float2(oacc[nt][2] * inv1, oacc[nt][3] * inv1);
    }
}

// ---------------------------------------------------------------------------
// 5) out = wo @ O + bo + x   (O in (B,N,C))
// ---------------------------------------------------------------------------
#define XS_LD 68
__global__ __launch_bounds__(256) void oproj_kernel(const float* __restrict__ wo,
                                                    const float* __restrict__ bo,
                                                    const float* __restrict__ x,
                                                    float* __restrict__ out) {
    __shared__ float Xs[64 * XS_LD];
    __shared__ float Wsm[CC * CC];
    int b = blockIdx.y;
    int i0 = blockIdx.x * 64;
    int tid = threadIdx.x;
    for (int t = tid; t < CC * CC / 4; t += 256)
        ((float4*)Wsm)[t] = ((const float4*)wo)[t];
    {
        int i = tid >> 2, q4 = tid & 3;
        const float* orow = g_o + (size_t)(b * NNPOS + i0 + i) * CC;
#pragma unroll
        for (int u = 0; u < 4; u++) {
            int c = q4 * 16 + u * 4;
            *(float4*)&Xs[i * XS_LD + c] = *(const float4*)&orow[c];
        }
    }
    __syncthreads();
    int to = tid >> 4, tx = tid & 15;
    float acc[4][4] = {};
#pragma unroll 4
    for (int c4 = 0; c4 < CC; c4 += 4) {
        float4 wv[4], xv[4];
#pragma unroll
        for (int r = 0; r < 4; r++) wv[r] = *(float4*)&Wsm[(to * 4 + r) * 64 + c4];
#pragma unroll
        for (int s = 0; s < 4; s++) xv[s] = *(float4*)&Xs[(tx * 4 + s) * XS_LD + c4];
#pragma unroll
        for (int r = 0; r < 4; r++)
#pragma unroll
            for (int s = 0; s < 4; s++)
                acc[r][s] += wv[r].x * xv[s].x + wv[r].y * xv[s].y +
                             wv[r].z * xv[s].z + wv[r].w * xv[s].w;
    }
#pragma unroll
    for (int r = 0; r < 4; r++) {
        int o = to * 4 + r;
        float bias = __ldg(&bo[o]);
        size_t base = (size_t)(b * CC + o) * NNPOS + i0 + tx * 4;
        float4 xr = *(const float4*)&x[base];
        float4 res = make_float4(acc[r][0] + bias + xr.x, acc[r][1] + bias + xr.y,
                                 acc[r][2] + bias + xr.z, acc[r][3] + bias + xr.w);
        *(float4*)&out[base] = res;
    }
}

// ---------------------------------------------------------------------------
extern "C" void kernel_launch(void* const* d_in, const int* in_sizes, int n_in,
                              void* d_out, int out_size) {
    (void)in_sizes; (void)n_in; (void)out_size;
    const float* x    = (const float*)d_in[0];
    const float* ln_g = (const float*)d_in[1];
    const float* ln_b = (const float*)d_in[2];
    const float* wq   = (const float*)d_in[3];
    const float* bq   = (const float*)d_in[4];
    const float* wk   = (const float*)d_in[5];
    const float* bk   = (const float*)d_in[6];
    const float* wv   = (const float*)d_in[7];
    const float* bv   = (const float*)d_in[8];
    const float* wo   = (const float*)d_in[9];
    const float* bo   = (const float*)d_in[10];
    float* out = (float*)d_out;

    ln_kernel<<<(BB * NNPOS) / 256, 256>>>(x, ln_g, ln_b);
    qproj_kernel<<<dim3(NNPOS / 64, BB), 256>>>(wq, bq);
    dwconv_kernel<<<dim3(NNPOS / 128, 4, BB), 128>>>(wk, bk, wv, bv);
    cudaFuncSetAttribute(attn_kernel, cudaFuncAttributeMaxDynamicSharedMemorySize, ATTN_SMEM);
    attn_kernel<<<dim3(NNPOS / 64, BB), 128, ATTN_SMEM>>>();
    oproj_kernel<<<dim3(NNPOS / 64, BB), 256>>>(wo, bo, x, out);
}

// round 6
// speedup vs baseline: 1.4421x; 1.4421x over previous
#include <cuda_runtime.h>
#include <cuda_fp16.h>
#include <cstdint>

#define BB 4
#define CC 64
#define NNPOS 4096
#define HH 64
#define WW 64

// Scratch (__device__ globals; no allocs allowed)
__device__ __half g_xn[BB * CC * NNPOS];           // LN output (B,C,N) fp16
__device__ __half g_q[BB * NNPOS * CC];            // Q fp16 (B,N,C), x (0.125*log2e) folded
__device__ __half g_k[BB * NNPOS * CC];            // K fp16 (B,N,C)
__device__ __half g_v[BB * CC * NNPOS];            // V fp16 (B,C,N)
__device__ float g_o[BB * NNPOS * CC];             // attn out (B,N,C) fp32

#define QSCALE 0.18033688011112293f   // 0.125 * log2(e)
#define ONES2 0x3C003C00u              // half2(1.0, 1.0)

// ---------------- helpers ----------------
__device__ __forceinline__ uint32_t h2u(__half2 h) { return *reinterpret_cast<uint32_t*>(&h); }

__device__ __forceinline__ void ldsm4(uint32_t* r, uint32_t addr) {
    asm volatile("ldmatrix.sync.aligned.m8n8.x4.shared.b16 {%0,%1,%2,%3}, [%4];"
                 : "=r"(r[0]), "=r"(r[1]), "=r"(r[2]), "=r"(r[3]) : "r"(addr));
}
__device__ __forceinline__ void mma16816(float* d, const uint32_t* a, uint32_t b0, uint32_t b1) {
    asm volatile("mma.sync.aligned.m16n8k16.row.col.f32.f16.f16.f32 "
                 "{%0,%1,%2,%3},{%4,%5,%6,%7},{%8,%9},{%0,%1,%2,%3};"
                 : "+f"(d[0]), "+f"(d[1]), "+f"(d[2]), "+f"(d[3])
                 : "r"(a[0]), "r"(a[1]), "r"(a[2]), "r"(a[3]), "r"(b0), "r"(b1));
}
__device__ __forceinline__ void cpasync16(uint32_t dst, const void* src) {
    asm volatile("cp.async.cg.shared.global [%0], [%1], 16;" :: "r"(dst), "l"(src));
}
__device__ __forceinline__ void cpcommit() { asm volatile("cp.async.commit_group;"); }
__device__ __forceinline__ void cpwait0()  { asm volatile("cp.async.wait_group 0;"); }

// p_f16x2 = 2^{slo, shi} via one cvt + one MUFU ex2 (pairwise)
__device__ __forceinline__ uint32_t exp2_f16x2(float slo, float shi) {
    uint32_t h, r;
    asm("cvt.rn.f16x2.f32 %0, %1, %2;" : "=r"(h) : "f"(shi), "f"(slo));
    asm("ex2.approx.f16x2 %0, %1;" : "=r"(r) : "r"(h));
    return r;
}

// ---------------------------------------------------------------------------
// 1) LayerNorm over channels -> g_xn (B,C,N) fp16
// ---------------------------------------------------------------------------
__global__ void ln_kernel(const float* __restrict__ x,
                          const float* __restrict__ g,
                          const float* __restrict__ be) {
    int idx = blockIdx.x * blockDim.x + threadIdx.x;
    int b = idx >> 12;
    int i = idx & 4095;
    const float* xp = x + (size_t)b * CC * NNPOS + i;
    float vals[CC];
    float s = 0.f;
#pragma unroll
    for (int c = 0; c < CC; c++) { vals[c] = xp[(size_t)c * NNPOS]; s += vals[c]; }
    float mu = s * (1.f / 64.f);
    float vs = 0.f;
#pragma unroll
    for (int c = 0; c < CC; c++) { float d = vals[c] - mu; vs += d * d; }
    float rstd = rsqrtf(vs * (1.f / 64.f) + 1e-5f);
    __half* op = g_xn + (size_t)b * CC * NNPOS + i;
#pragma unroll
    for (int c = 0; c < CC; c++)
        op[(size_t)c * NNPOS] = __float2half_rn((vals[c] - mu) * rstd * __ldg(&g[c]) + __ldg(&be[c]));
}

// ---------------------------------------------------------------------------
// 2) q = (wq @ xn + bq) * QSCALE -> fp16 (B,N,C)
// ---------------------------------------------------------------------------
__global__ __launch_bounds__(256) void qproj_kernel(const float* __restrict__ wq,
                                                    const float* __restrict__ bq) {
    __shared__ float Xs[CC * 64];
    __shared__ float Wsm[CC * CC];
    int b = blockIdx.y;
    int i0 = blockIdx.x * 64;
    int tid = threadIdx.x;
    for (int t = tid; t < CC * CC / 4; t += 256)
        ((float4*)Wsm)[t] = ((const float4*)wq)[t];
    const __half* xp = g_xn + (size_t)b * CC * NNPOS + i0;
    for (int t = tid; t < CC * 16; t += 256) {
        int c = t >> 4, f = t & 15;
        uint2 raw = *(const uint2*)&xp[(size_t)c * NNPOS + f * 4];
        __half2 ha = *(__half2*)&raw.x, hb = *(__half2*)&raw.y;
        float2 fa = __half22float2(ha), fb = __half22float2(hb);
        *(float4*)&Xs[c * 64 + f * 4] = make_float4(fa.x, fa.y, fb.x, fb.y);
    }
    __syncthreads();
    int to = tid >> 4, tx = tid & 15;
    float acc[4][4] = {};
#pragma unroll 8
    for (int c = 0; c < CC; c++) {
        float4 xv = *(float4*)&Xs[c * 64 + tx * 4];
        float w0 = Wsm[(to * 4 + 0) * 64 + c];
        float w1 = Wsm[(to * 4 + 1) * 64 + c];
        float w2 = Wsm[(to * 4 + 2) * 64 + c];
        float w3 = Wsm[(to * 4 + 3) * 64 + c];
        acc[0][0] += w0 * xv.x; acc[0][1] += w0 * xv.y; acc[0][2] += w0 * xv.z; acc[0][3] += w0 * xv.w;
        acc[1][0] += w1 * xv.x; acc[1][1] += w1 * xv.y; acc[1][2] += w1 * xv.z; acc[1][3] += w1 * xv.w;
        acc[2][0] += w2 * xv.x; acc[2][1] += w2 * xv.y; acc[2][2] += w2 * xv.z; acc[2][3] += w2 * xv.w;
        acc[3][0] += w3 * xv.x; acc[3][1] += w3 * xv.y; acc[3][2] += w3 * xv.z; acc[3][3] += w3 * xv.w;
    }
    float bb[4];
#pragma unroll
    for (int r = 0; r < 4; r++) bb[r] = __ldg(&bq[to * 4 + r]);
#pragma unroll
    for (int s = 0; s < 4; s++) {
        int i = i0 + tx * 4 + s;
        float v0 = (acc[0][s] + bb[0]) * QSCALE;
        float v1 = (acc[1][s] + bb[1]) * QSCALE;
        float v2 = (acc[2][s] + bb[2]) * QSCALE;
        float v3 = (acc[3][s] + bb[3]) * QSCALE;
        size_t base = (size_t)(b * NNPOS + i) * CC + to * 4;
        *(uint2*)&g_q[base] = make_uint2(h2u(__floats2half2_rn(v0, v1)),
                                         h2u(__floats2half2_rn(v2, v3)));
    }
}

// ---------------------------------------------------------------------------
// 3) Depthwise 3x3: k -> fp16 (B,N,C), v -> fp16 (B,C,N)
// ---------------------------------------------------------------------------
__global__ __launch_bounds__(128) void dwconv_kernel(const float* __restrict__ wk,
                                                     const float* __restrict__ bk,
                                                     const float* __restrict__ wv,
                                                     const float* __restrict__ bv) {
    int t = threadIdx.x;
    int pos = blockIdx.x * 128 + t;
    int cg = blockIdx.y * 16;
    int b = blockIdx.z;
    int h = pos >> 6, w = pos & 63;
    uint32_t khp[8];
    uint32_t khprev = 0;
#pragma unroll
    for (int ci = 0; ci < 16; ci++) {
        int c = cg + ci;
        const __half* xp = g_xn + (size_t)(b * CC + c) * NNPOS;
        const float* wkp = wk + c * 9;
        const float* wvp = wv + c * 9;
        float sk = __ldg(&bk[c]);
        float sv = __ldg(&bv[c]);
#pragma unroll
        for (int dh = 0; dh < 3; dh++) {
            int hh = h + dh - 1;
            if (hh < 0 || hh >= HH) continue;
#pragma unroll
            for (int dw = 0; dw < 3; dw++) {
                int ww = w + dw - 1;
                if (ww < 0 || ww >= WW) continue;
                float xv = __half2float(xp[hh * WW + ww]);
                sk += xv * __ldg(&wkp[dh * 3 + dw]);
                sv += xv * __ldg(&wvp[dh * 3 + dw]);
            }
        }
        g_v[(size_t)(b * CC + c) * NNPOS + pos] = __float2half_rn(sv);
        uint32_t hb = (uint32_t)__half_as_ushort(__float2half_rn(sk));
        if (ci & 1) khp[ci >> 1] = khprev | (hb << 16);
        else khprev = hb;
    }
    size_t kbase = (size_t)(b * NNPOS + pos) * CC + cg;
    *(uint4*)&g_k[kbase]     = make_uint4(khp[0], khp[1], khp[2], khp[3]);
    *(uint4*)&g_k[kbase + 8] = make_uint4(khp[4], khp[5], khp[6], khp[7]);
}

// ---------------------------------------------------------------------------
// 4) HMMA flash attention, fp16 operands, fp32 accum.
//    grid (32, B) = 128 blocks, 256 threads = 8 warps x 16 query rows.
//    K tile 128x(128B+16), V tile 64x(256B+16), double buffered.
//    softmax: ex2.approx.f16x2 (MUFU, pairwise); l via MMA against ones.
// ---------------------------------------------------------------------------
#define KROWB 144
#define VROWB 272
#define KBYTES (128 * KROWB)        // 18432
#define VBYTES (64 * VROWB)         // 17408
#define BUFB (KBYTES + VBYTES)      // 35840
#define ATTN_SMEM (2 * BUFB)        // 71680

__device__ __forceinline__ void prefetch_tile(char* smp, int s, int b, int jt, int tid) {
    // K: 128 rows x 128B. thread -> row j = tid>>1, half hf = tid&1 (64B)
    {
        int j = tid >> 1, hf = tid & 1;
        const __half* src = g_k + (size_t)(b * NNPOS + jt + j) * CC + hf * 32;
        uint32_t dst = (uint32_t)__cvta_generic_to_shared(smp + s * BUFB + j * KROWB + hf * 64);
#pragma unroll
        for (int u = 0; u < 4; u++) cpasync16(dst + u * 16, src + u * 8);
    }
    // V: 64 rows x 256B. thread -> row c = tid>>2, quarter q = tid&3 (64B)
    {
        int c = tid >> 2, q = tid & 3;
        const __half* src = g_v + (size_t)(b * CC + c) * NNPOS + jt + q * 32;
        uint32_t dst = (uint32_t)__cvta_generic_to_shared(smp + s * BUFB + KBYTES + c * VROWB + q * 64);
#pragma unroll
        for (int u = 0; u < 4; u++) cpasync16(dst + u * 16, src + u * 8);
    }
}

__global__ __launch_bounds__(256, 1) void attn_kernel() {
    extern __shared__ char smp[];
    int tid = threadIdx.x;
    int w = tid >> 5, lane = tid & 31;
    int b = blockIdx.y;
    int i0 = blockIdx.x * 128;
    int g = lane >> 2, t4 = lane & 3;

    // B-type ldmatrix.x4 lane offset pieces
    int laneRowB = (lane & 7) + ((lane & 16) >> 1);
    int laneKB   = (lane & 8) << 1;
    uint32_t loffK = (uint32_t)(laneRowB * KROWB + laneKB);
    uint32_t loffV = (uint32_t)(laneRowB * VROWB + laneKB);
    uint32_t smbase = (uint32_t)__cvta_generic_to_shared(smp);

    prefetch_tile(smp, 0, b, 0, tid);
    cpcommit();

    // Q A-fragments resident: qA[ks][0..3], ks = 0..3 (K=64)
    uint32_t qA[4][4];
    {
        size_t row0 = (size_t)(b * NNPOS + i0 + w * 16 + g) * CC;
        size_t row8 = row0 + 8 * CC;
#pragma unroll
        for (int ks = 0; ks < 4; ks++) {
            int col = 2 * t4 + 16 * ks;
            qA[ks][0] = *(const uint32_t*)(g_q + row0 + col);
            qA[ks][1] = *(const uint32_t*)(g_q + row8 + col);
            qA[ks][2] = *(const uint32_t*)(g_q + row0 + col + 8);
            qA[ks][3] = *(const uint32_t*)(g_q + row8 + col + 8);
        }
    }

    float oacc[8][4] = {};
    float lacc[4] = {};   // row-sums of P via MMA with ones (exact fp32)

    for (int tix = 0; tix < 32; tix++) {
        cpwait0();
        __syncthreads();
        if (tix < 31) { prefetch_tile(smp, (tix + 1) & 1, b, (tix + 1) * 128, tid); cpcommit(); }

        uint32_t kb = smbase + (uint32_t)((tix & 1) * BUFB) + loffK;
        uint32_t vb = smbase + (uint32_t)((tix & 1) * BUFB + KBYTES) + loffV;

        // ---- S = Q K^T : M=16 x N=128, K=64, ldsm double-buffered ----
        float sacc[16][4] = {};
        {
            uint32_t b4[2][4];
            ldsm4(b4[0], kb);
#pragma unroll
            for (int it = 0; it < 32; it++) {
                int ks = it >> 3, np = it & 7;
                int cur = it & 1;
                if (it < 31) {
                    int nx = it + 1;
                    ldsm4(b4[cur ^ 1], kb + (uint32_t)((nx & 7) * (16 * KROWB) + (nx >> 3) * 32));
                }
                mma16816(sacc[2 * np],     qA[ks], b4[cur][0], b4[cur][1]);
                mma16816(sacc[2 * np + 1], qA[ks], b4[cur][2], b4[cur][3]);
            }
        }

        // ---- p = 2^S (cvt + MUFU ex2.f16x2), l via ones-MMA, O += P V^T ----
        {
            uint32_t v4[2][4];
            ldsm4(v4[0], vb);
#pragma unroll
            for (int ks2 = 0; ks2 < 8; ks2++) {
                uint32_t pA[4];
                {
                    float* se = sacc[2 * ks2];
                    float* so = sacc[2 * ks2 + 1];
                    pA[0] = exp2_f16x2(se[0], se[1]);
                    pA[1] = exp2_f16x2(se[2], se[3]);
                    pA[2] = exp2_f16x2(so[0], so[1]);
                    pA[3] = exp2_f16x2(so[2], so[3]);
                }
                mma16816(lacc, pA, ONES2, ONES2);   // row-sums (all cols identical)
#pragma unroll
                for (int np = 0; np < 4; np++) {
                    int it = ks2 * 4 + np;
                    int cur = it & 1;
                    if (it < 31) {
                        int nx = it + 1;
                        ldsm4(v4[cur ^ 1], vb + (uint32_t)((nx & 3) * (16 * VROWB) + (nx >> 2) * 32));
                    }
                    mma16816(oacc[2 * np],     pA, v4[cur][0], v4[cur][1]);
                    mma16816(oacc[2 * np + 1], pA, v4[cur][2], v4[cur][3]);
                }
            }
        }
    }

    // lacc[0] = rowsum(row g), lacc[2] = rowsum(row g+8) — already complete per lane
    float inv0 = 1.f / lacc[0], inv1 = 1.f / lacc[2];

    float* orow0 = g_o + (size_t)(b * NNPOS + i0 + w * 16 + g) * CC;
    float* orow8 = orow0 + 8 * CC;
#pragma unroll
    for (int nt = 0; nt < 8; nt++) {
        int c = nt * 8 + 2 * t4;
        *(float2*)&orow0[c] = make_float2(oacc[nt][0] * inv0, oacc[nt][1] * inv0);
        *(float2*)&orow8[c] = make_float2(oacc[nt][2] * inv1, oacc[nt][3] * inv1);
    }
}

// ---------------------------------------------------------------------------
// 5) out = wo @ O + bo + x   (O in (B,N,C))
// ---------------------------------------------------------------------------
#define XS_LD 68
__global__ __launch_bounds__(256) void oproj_kernel(const float* __restrict__ wo,
                                                    const float* __restrict__ bo,
                                                    const float* __restrict__ x,
                                                    float* __restrict__ out) {
    __shared__ float Xs[64 * XS_LD];
    __shared__ float Wsm[CC * CC];
    int b = blockIdx.y;
    int i0 = blockIdx.x * 64;
    int tid = threadIdx.x;
    for (int t = tid; t < CC * CC / 4; t += 256)
        ((float4*)Wsm)[t] = ((const float4*)wo)[t];
    {
        int i = tid >> 2, q4 = tid & 3;
        const float* orow = g_o + (size_t)(b * NNPOS + i0 + i) * CC;
#pragma unroll
        for (int u = 0; u < 4; u++) {
            int c = q4 * 16 + u * 4;
            *(float4*)&Xs[i * XS_LD + c] = *(const float4*)&orow[c];
        }
    }
    __syncthreads();
    int to = tid >> 4, tx = tid & 15;
    float acc[4][4] = {};
#pragma unroll 4
    for (int c4 = 0; c4 < CC; c4 += 4) {
        float4 wv[4], xv[4];
#pragma unroll
        for (int r = 0; r < 4; r++) wv[r] = *(float4*)&Wsm[(to * 4 + r) * 64 + c4];
#pragma unroll
        for (int s = 0; s < 4; s++) xv[s] = *(float4*)&Xs[(tx * 4 + s) * XS_LD + c4];
#pragma unroll
        for (int r = 0; r < 4; r++)
#pragma unroll
            for (int s = 0; s < 4; s++)
                acc[r][s] += wv[r].x * xv[s].x + wv[r].y * xv[s].y +
                             wv[r].z * xv[s].z + wv[r].w * xv[s].w;
    }
#pragma unroll
    for (int r = 0; r < 4; r++) {
        int o = to * 4 + r;
        float bias = __ldg(&bo[o]);
        size_t base = (size_t)(b * CC + o) * NNPOS + i0 + tx * 4;
        float4 xr = *(const float4*)&x[base];
        float4 res = make_float4(acc[r][0] + bias + xr.x, acc[r][1] + bias + xr.y,
                                 acc[r][2] + bias + xr.z, acc[r][3] + bias + xr.w);
        *(float4*)&out[base] = res;
    }
}

// ---------------------------------------------------------------------------
extern "C" void kernel_launch(void* const* d_in, const int* in_sizes, int n_in,
                              void* d_out, int out_size) {
    (void)in_sizes; (void)n_in; (void)out_size;
    const float* x    = (const float*)d_in[0];
    const float* ln_g = (const float*)d_in[1];
    const float* ln_b = (const float*)d_in[2];
    const float* wq   = (const float*)d_in[3];
    const float* bq   = (const float*)d_in[4];
    const float* wk   = (const float*)d_in[5];
    const float* bk   = (const float*)d_in[6];
    const float* wv   = (const float*)d_in[7];
    const float* bv   = (const float*)d_in[8];
    const float* wo   = (const float*)d_in[9];
    const float* bo   = (const float*)d_in[10];
    float* out = (float*)d_out;

    ln_kernel<<<(BB * NNPOS) / 256, 256>>>(x, ln_g, ln_b);
    qproj_kernel<<<dim3(NNPOS / 64, BB), 256>>>(wq, bq);
    dwconv_kernel<<<dim3(NNPOS / 128, 4, BB), 128>>>(wk, bk, wv, bv);
    cudaFuncSetAttribute(attn_kernel, cudaFuncAttributeMaxDynamicSharedMemorySize, ATTN_SMEM);
    attn_kernel<<<dim3(NNPOS / 128, BB), 256, ATTN_SMEM>>>();
    oproj_kernel<<<dim3(NNPOS / 64, BB), 256>>>(wo, bo, x, out);
}